// round 3
// baseline (speedup 1.0000x reference)
#include <cuda_runtime.h>

// LengthRegulator: out[b, t, :] = x[b, j, :] where token j owns frame t,
// i.e. cum[b][j-1] <= t < cum[b][j]; zero for t >= cum[b][L-1].
// Second output: durations echoed back (as float, per the harness' single
// __output__ dtype). Shapes: N=16, L=512, D=384, T=3584.

#define NB 16
#define LL 512
#define DD 384
#define V4 (DD / 4)                      // 96 float4 per frame
#define FRAMES_PER_BLK 4
#define THREADS (V4 * FRAMES_PER_BLK)    // 384

// Scratch (allocation-free rule: __device__ globals).
__device__ int g_cum[NB * LL];           // inclusive cumsum of durations
__device__ int g_idx[NB * 4096];         // frame -> token map (T <= 4096)

// ---------------------------------------------------------------------------
// Kernel A: per-batch inclusive cumsum. 16 blocks x 32 lanes.
// ---------------------------------------------------------------------------
__global__ void lr_scan_kernel(const int* __restrict__ dur) {
    const int b = blockIdx.x;
    const int lane = threadIdx.x;        // 0..31
    const int base = b * LL + lane * 16;

    int local[16];
    int s = 0;
#pragma unroll
    for (int k = 0; k < 16; ++k) {
        s += dur[base + k];
        local[k] = s;                    // inclusive within chunk
    }

    int inc = s;
#pragma unroll
    for (int off = 1; off < 32; off <<= 1) {
        int v = __shfl_up_sync(0xffffffffu, inc, off);
        if (lane >= off) inc += v;
    }
    const int excl = inc - s;

#pragma unroll
    for (int k = 0; k < 16; ++k)
        g_cum[base + k] = local[k] + excl;
}

// ---------------------------------------------------------------------------
// Kernel B: scatter frame->token map. 16 blocks x 512 threads (one per token).
// ---------------------------------------------------------------------------
__global__ void lr_scatter_kernel(const int* __restrict__ dur) {
    const int b = blockIdx.x;
    const int j = threadIdx.x;
    const int c = g_cum[b * LL + j];
    const int d = dur[b * LL + j];
    const int start = c - d;
    int* row = g_idx + b * 4096;
    for (int k = 0; k < d; ++k)
        row[start + k] = j;
}

// ---------------------------------------------------------------------------
// Kernel C: expand. grid = (T/4, N), block = 384 threads.
// 96 lanes per frame: broadcast token-id load, float4 gather, coalesced store.
// ---------------------------------------------------------------------------
__global__ void lr_expand_kernel(const float* __restrict__ x,
                                 float* __restrict__ out, int T) {
    const int b = blockIdx.y;
    const int tid = threadIdx.x;
    const int f = tid / V4;              // 0..3
    const int v = tid % V4;              // 0..95
    const int t = blockIdx.x * FRAMES_PER_BLK + f;

    const int total = g_cum[b * LL + (LL - 1)];

    float4 val = make_float4(0.f, 0.f, 0.f, 0.f);
    if (t < total) {
        const int j = g_idx[b * 4096 + t];
        val = reinterpret_cast<const float4*>(
                  x + ((size_t)b * LL + j) * DD)[v];
    }
    reinterpret_cast<float4*>(out + ((size_t)b * T + t) * DD)[v] = val;
}

// ---------------------------------------------------------------------------
// Kernel D: echo durations as FLOAT (harness output buffer is float32).
// ---------------------------------------------------------------------------
__global__ void lr_copy_dur_kernel(const int* __restrict__ dur,
                                   float* __restrict__ dst, int n) {
    int i = blockIdx.x * blockDim.x + threadIdx.x;
    if (i < n) dst[i] = (float)dur[i];
}

extern "C" void kernel_launch(void* const* d_in, const int* in_sizes, int n_in,
                              void* d_out, int out_size) {
    const float* x = (const float*)d_in[0];
    const int* dur = (const int*)d_in[1];

    const int NL = NB * LL;                          // 8192
    const long long per_frame = (long long)NB * DD;  // 6144 elems per time step

    long long main_elems = out_size;
    bool echo = false;
    if (main_elems % per_frame != 0) {
        main_elems -= NL;
        echo = true;
    }
    const int T = (int)(main_elems / per_frame);     // 3584

    lr_scan_kernel<<<NB, 32>>>(dur);
    lr_scatter_kernel<<<NB, LL>>>(dur);

    dim3 grid(T / FRAMES_PER_BLK, NB);
    lr_expand_kernel<<<grid, THREADS>>>(x, (float*)d_out, T);

    if (echo) {
        float* dst = (float*)d_out + main_elems;
        lr_copy_dur_kernel<<<(NL + 255) / 256, 256>>>(dur, dst, NL);
    }
}